// round 1
// baseline (speedup 1.0000x reference)
#include <cuda_runtime.h>

#define HH 256
#define WW 256
#define NF 13776
#define NV 6890
#define BATCH 2
#define BIGF 1000000000.0f
#define EPSF 1e-8f
#define TILE 16
#define CULL 256
#define NWARPS 8

// Precomputed per-(batch,face) data (SoA, device scratch — no allocs)
__device__ float4 g_fa[BATCH * NF];       // A0*inv, B0*inv, A1*inv, B1*inv
__device__ float4 g_fb[BATCH * NF];       // x2, y2, z0, z1
__device__ float2 g_fc[BATCH * NF];       // z2, face_index (as int bits)
__device__ float4 g_bb[BATCH * NF];       // xmin, xmax, ymin, ymax (padded; empty if degenerate)
__device__ float2 g_sf[BATCH * NF * 3];   // src flow per corner (sx, sy)

__global__ void setup_kernel(const float* __restrict__ src_cam,
                             const float* __restrict__ src_verts,
                             const float* __restrict__ tgt_cam,
                             const float* __restrict__ tgt_verts,
                             const int*   __restrict__ faces)
{
    int idx = blockIdx.x * blockDim.x + threadIdx.x;
    if (idx >= BATCH * NF) return;
    int b = idx / NF;
    int f = idx - b * NF;

    int i0 = faces[f * 3 + 0];
    int i1 = faces[f * 3 + 1];
    int i2 = faces[f * 3 + 2];

    float tc0 = tgt_cam[b * 3 + 0];
    float tc1 = tgt_cam[b * 3 + 1];
    float tc2 = tgt_cam[b * 3 + 2];
    const float* tv = tgt_verts + (size_t)b * NV * 3;

    // project: x = c0*(vx+c1); y = -(c0*(vy+c2)); z = vz   (match ref op order)
    float x0 = tc0 * (tv[i0 * 3 + 0] + tc1);
    float y0 = -(tc0 * (tv[i0 * 3 + 1] + tc2));
    float z0 = tv[i0 * 3 + 2];
    float x1 = tc0 * (tv[i1 * 3 + 0] + tc1);
    float y1 = -(tc0 * (tv[i1 * 3 + 1] + tc2));
    float z1 = tv[i1 * 3 + 2];
    float x2 = tc0 * (tv[i2 * 3 + 0] + tc1);
    float y2 = -(tc0 * (tv[i2 * 3 + 1] + tc2));
    float z2 = tv[i2 * 3 + 2];

    float denom = (y1 - y2) * (x0 - x2) + (x2 - x1) * (y0 - y2);
    bool valid = fabsf(denom) >= EPSF;
    float inv = 1.0f / (valid ? denom : 1.0f);

    g_fa[idx] = make_float4((y1 - y2) * inv, (x2 - x1) * inv,
                            (y2 - y0) * inv, (x0 - x2) * inv);
    g_fb[idx] = make_float4(x2, y2, z0, z1);
    g_fc[idx] = make_float2(z2, __int_as_float(f));

    const float pad = 2.0f / 256.0f;  // one pixel of slack
    float xmn = fminf(x0, fminf(x1, x2)) - pad;
    float xmx = fmaxf(x0, fmaxf(x1, x2)) + pad;
    float ymn = fminf(y0, fminf(y1, y2)) - pad;
    float ymx = fmaxf(y0, fmaxf(y1, y2)) + pad;
    if (!valid) { xmn = 1e30f; xmx = -1e30f; ymn = 1e30f; ymx = -1e30f; }
    g_bb[idx] = make_float4(xmn, xmx, ymn, ymx);

    float sc0 = src_cam[b * 3 + 0];
    float sc1 = src_cam[b * 3 + 1];
    float sc2 = src_cam[b * 3 + 2];
    const float* sv = src_verts + (size_t)b * NV * 3;
    // src_f2v: (c0*(x+c1), c0*(y+c2))  [double negation cancels on y]
    g_sf[idx * 3 + 0] = make_float2(sc0 * (sv[i0 * 3 + 0] + sc1), sc0 * (sv[i0 * 3 + 1] + sc2));
    g_sf[idx * 3 + 1] = make_float2(sc0 * (sv[i1 * 3 + 0] + sc1), sc0 * (sv[i1 * 3 + 1] + sc2));
    g_sf[idx * 3 + 2] = make_float2(sc0 * (sv[i2 * 3 + 0] + sc1), sc0 * (sv[i2 * 3 + 1] + sc2));
}

__global__ __launch_bounds__(256) void raster_kernel(const float* __restrict__ src_img,
                                                     float* __restrict__ out)
{
    __shared__ float4 s_fa[CULL];
    __shared__ float4 s_fb[CULL];
    __shared__ float2 s_fc[CULL];
    __shared__ int    s_wcnt[NWARPS];

    const int b     = blockIdx.y;
    const int tileX = blockIdx.x & 15;
    const int tileY = blockIdx.x >> 4;
    const int tid   = threadIdx.x;
    const int lane  = tid & 31;
    const int warp  = tid >> 5;

    const int px_i = tileX * TILE + (tid & 15);
    const int py_i = tileY * TILE + (tid >> 4);
    const float px = ((float)px_i + 0.5f) / 256.0f * 2.0f - 1.0f;
    const float py = ((float)py_i + 0.5f) / 256.0f * 2.0f - 1.0f;

    // tile bbox in NDC (pixel centers)
    const float tx0 = ((float)(tileX * TILE)            + 0.5f) / 256.0f * 2.0f - 1.0f;
    const float tx1 = ((float)(tileX * TILE + TILE - 1) + 0.5f) / 256.0f * 2.0f - 1.0f;
    const float ty0 = ((float)(tileY * TILE)            + 0.5f) / 256.0f * 2.0f - 1.0f;
    const float ty1 = ((float)(tileY * TILE + TILE - 1) + 0.5f) / 256.0f * 2.0f - 1.0f;

    const float4* __restrict__ fa = g_fa + b * NF;
    const float4* __restrict__ fb = g_fb + b * NF;
    const float2* __restrict__ fc = g_fc + b * NF;
    const float4* __restrict__ bb = g_bb + b * NF;

    float zmin = BIGF;
    int   best = -1;

    for (int base = 0; base < NF; base += CULL) {
        int f = base + tid;
        bool pass = false;
        if (f < NF) {
            float4 bx = bb[f];
            pass = (bx.x <= tx1) & (bx.y >= tx0) & (bx.z <= ty1) & (bx.w >= ty0);
        }
        unsigned m = __ballot_sync(0xffffffffu, pass);
        if (lane == 0) s_wcnt[warp] = __popc(m);
        __syncthreads();

        int off = 0;
        int cnt = 0;
        #pragma unroll
        for (int w = 0; w < NWARPS; w++) {
            int c = s_wcnt[w];
            if (w < warp) off += c;
            cnt += c;
        }
        off += __popc(m & ((1u << lane) - 1u));
        if (pass) {
            s_fa[off] = fa[f];
            s_fb[off] = fb[f];
            s_fc[off] = fc[f];
        }
        __syncthreads();

        for (int k = 0; k < cnt; k++) {
            float4 a  = s_fa[k];
            float4 c4 = s_fb[k];
            float2 e  = s_fc[k];
            float dx = px - c4.x;
            float dy = py - c4.y;
            float w0 = fmaf(a.x, dx, a.y * dy);
            float w1 = fmaf(a.z, dx, a.w * dy);
            float w2 = 1.0f - w0 - w1;
            float mn = fminf(fminf(w0, w1), w2);
            float depth = fmaf(w0, c4.z, fmaf(w1, c4.w, w2 * e.x));
            float d2 = (mn >= 0.0f) ? depth : BIGF;
            if (d2 < zmin) { zmin = d2; best = __float_as_int(e.y); }
        }
        __syncthreads();
    }

    // epilogue: flow for this pixel
    float fx, fy;
    if (best >= 0) {
        int gi = b * NF + best;
        float4 a  = g_fa[gi];
        float4 c4 = g_fb[gi];
        float dx = px - c4.x;
        float dy = py - c4.y;
        float w0 = fmaf(a.x, dx, a.y * dy);
        float w1 = fmaf(a.z, dx, a.w * dy);
        float w2 = 1.0f - w0 - w1;
        float2 s0 = g_sf[gi * 3 + 0];
        float2 s1 = g_sf[gi * 3 + 1];
        float2 s2 = g_sf[gi * 3 + 2];
        fx = w0 * s0.x + w1 * s1.x + w2 * s2.x;
        fy = w0 * s0.y + w1 * s1.y + w2 * s2.y;
    } else {
        fx = -2.0f;
        fy = -2.0f;
    }

    // bilinear grid sample with border clamp
    float ix = fminf(fmaxf(((fx + 1.0f) * 256.0f - 1.0f) * 0.5f, 0.0f), 255.0f);
    float iy = fminf(fmaxf(((fy + 1.0f) * 256.0f - 1.0f) * 0.5f, 0.0f), 255.0f);
    float x0f = floorf(ix);
    float y0f = floorf(iy);
    float wx = ix - x0f;
    float wy = iy - y0f;
    int x0i = (int)x0f;
    int y0i = (int)y0f;
    int x1i = min(x0i + 1, WW - 1);
    int y1i = min(y0i + 1, HH - 1);

    float wa = (1.0f - wx) * (1.0f - wy);
    float wb = wx * (1.0f - wy);
    float wc = (1.0f - wx) * wy;
    float wd = wx * wy;

    const float* img = src_img + (size_t)b * 3 * HH * WW;
    #pragma unroll
    for (int c = 0; c < 3; c++) {
        const float* p = img + (size_t)c * HH * WW;
        float Ia = p[y0i * WW + x0i];
        float Ib = p[y0i * WW + x1i];
        float Ic = p[y1i * WW + x0i];
        float Id = p[y1i * WW + x1i];
        out[(((size_t)b * 3 + c) * HH + py_i) * WW + px_i] =
            Ia * wa + Ib * wb + Ic * wc + Id * wd;
    }
}

extern "C" void kernel_launch(void* const* d_in, const int* in_sizes, int n_in,
                              void* d_out, int out_size)
{
    const float* src_img   = (const float*)d_in[0];
    const float* src_cam   = (const float*)d_in[1];
    const float* src_verts = (const float*)d_in[2];
    const float* tgt_cam   = (const float*)d_in[3];
    const float* tgt_verts = (const float*)d_in[4];
    const int*   faces     = (const int*)d_in[5];
    float* out = (float*)d_out;

    int n = BATCH * NF;
    setup_kernel<<<(n + 255) / 256, 256>>>(src_cam, src_verts, tgt_cam, tgt_verts, faces);
    dim3 grid(256, BATCH);
    raster_kernel<<<grid, 256>>>(src_img, out);
}

// round 2
// speedup vs baseline: 3.1644x; 3.1644x over previous
#include <cuda_runtime.h>

#define HH 256
#define WW 256
#define PP (HH * WW)
#define NF 13776
#define NV 6890
#define BATCH 2
#define BIGF 1000000000.0f
#define EPSF 1e-8f
#define TILE 16
#define NSEG 8
#define SEGLEN ((NF + NSEG - 1) / NSEG)
#define CULL 128
#define NWARPS 4

// Precomputed per-(batch,face) data (SoA, device scratch — no allocs)
__device__ float4 g_fa[BATCH * NF];       // A0*inv, B0*inv, A1*inv, B1*inv
__device__ float4 g_fb[BATCH * NF];       // x2, y2, z0, z1
__device__ float2 g_fc[BATCH * NF];       // z2, face_index (as int bits)
__device__ float4 g_bb[BATCH * NF];       // xmin, xmax, ymin, ymax (empty if degenerate)
__device__ float2 g_sf[BATCH * NF * 3];   // src flow per corner (sx, sy)
__device__ unsigned long long g_zb[BATCH * PP];  // packed (sortable depth << 32) | face

__device__ __forceinline__ unsigned int f2sortable(float d) {
    unsigned int u = __float_as_uint(d);
    return u ^ (((unsigned int)((int)u >> 31)) | 0x80000000u);
}

__global__ void setup_kernel(const float* __restrict__ src_cam,
                             const float* __restrict__ src_verts,
                             const float* __restrict__ tgt_cam,
                             const float* __restrict__ tgt_verts,
                             const int*   __restrict__ faces)
{
    int idx = blockIdx.x * blockDim.x + threadIdx.x;
    if (idx >= BATCH * NF) return;
    int b = idx / NF;
    int f = idx - b * NF;

    int i0 = faces[f * 3 + 0];
    int i1 = faces[f * 3 + 1];
    int i2 = faces[f * 3 + 2];

    float tc0 = tgt_cam[b * 3 + 0];
    float tc1 = tgt_cam[b * 3 + 1];
    float tc2 = tgt_cam[b * 3 + 2];
    const float* tv = tgt_verts + (size_t)b * NV * 3;

    float x0 = tc0 * (tv[i0 * 3 + 0] + tc1);
    float y0 = -(tc0 * (tv[i0 * 3 + 1] + tc2));
    float z0 = tv[i0 * 3 + 2];
    float x1 = tc0 * (tv[i1 * 3 + 0] + tc1);
    float y1 = -(tc0 * (tv[i1 * 3 + 1] + tc2));
    float z1 = tv[i1 * 3 + 2];
    float x2 = tc0 * (tv[i2 * 3 + 0] + tc1);
    float y2 = -(tc0 * (tv[i2 * 3 + 1] + tc2));
    float z2 = tv[i2 * 3 + 2];

    float denom = (y1 - y2) * (x0 - x2) + (x2 - x1) * (y0 - y2);
    bool valid = fabsf(denom) >= EPSF;
    float inv = 1.0f / (valid ? denom : 1.0f);

    g_fa[idx] = make_float4((y1 - y2) * inv, (x2 - x1) * inv,
                            (y2 - y0) * inv, (x0 - x2) * inv);
    g_fb[idx] = make_float4(x2, y2, z0, z1);
    g_fc[idx] = make_float2(z2, __int_as_float(f));

    const float pad = 2.0f / 256.0f;
    float xmn = fminf(x0, fminf(x1, x2)) - pad;
    float xmx = fmaxf(x0, fmaxf(x1, x2)) + pad;
    float ymn = fminf(y0, fminf(y1, y2)) - pad;
    float ymx = fmaxf(y0, fmaxf(y1, y2)) + pad;
    if (!valid) { xmn = 1e30f; xmx = -1e30f; ymn = 1e30f; ymx = -1e30f; }
    g_bb[idx] = make_float4(xmn, xmx, ymn, ymx);

    float sc0 = src_cam[b * 3 + 0];
    float sc1 = src_cam[b * 3 + 1];
    float sc2 = src_cam[b * 3 + 2];
    const float* sv = src_verts + (size_t)b * NV * 3;
    g_sf[idx * 3 + 0] = make_float2(sc0 * (sv[i0 * 3 + 0] + sc1), sc0 * (sv[i0 * 3 + 1] + sc2));
    g_sf[idx * 3 + 1] = make_float2(sc0 * (sv[i1 * 3 + 0] + sc1), sc0 * (sv[i1 * 3 + 1] + sc2));
    g_sf[idx * 3 + 2] = make_float2(sc0 * (sv[i2 * 3 + 0] + sc1), sc0 * (sv[i2 * 3 + 1] + sc2));
}

__global__ void zinit_kernel()
{
    int i = blockIdx.x * blockDim.x + threadIdx.x;
    if (i >= BATCH * PP) return;
    unsigned long long init =
        ((unsigned long long)f2sortable(BIGF) << 32) | 0xFFFFFFFFull;
    g_zb[i] = init;
}

__global__ __launch_bounds__(CULL) void raster_kernel()
{
    __shared__ float4 s_fa[CULL];
    __shared__ float4 s_fb[CULL];
    __shared__ float2 s_fc[CULL];
    __shared__ int    s_wcnt[NWARPS];

    const int b     = blockIdx.z;
    const int seg   = blockIdx.y;
    const int tileX = blockIdx.x & 15;
    const int tileY = blockIdx.x >> 4;
    const int tid   = threadIdx.x;
    const int lane  = tid & 31;
    const int warp  = tid >> 5;

    // two adjacent pixels per thread (row-major within 16x16 tile)
    const int p0    = tid * 2;
    const int px0_i = tileX * TILE + (p0 & 15);
    const int px1_i = px0_i + 1;
    const int py_i  = tileY * TILE + (p0 >> 4);
    const float px0 = ((float)px0_i + 0.5f) / 256.0f * 2.0f - 1.0f;
    const float px1 = ((float)px1_i + 0.5f) / 256.0f * 2.0f - 1.0f;
    const float py  = ((float)py_i + 0.5f) / 256.0f * 2.0f - 1.0f;

    const float tx0 = ((float)(tileX * TILE)            + 0.5f) / 256.0f * 2.0f - 1.0f;
    const float tx1 = ((float)(tileX * TILE + TILE - 1) + 0.5f) / 256.0f * 2.0f - 1.0f;
    const float ty0 = ((float)(tileY * TILE)            + 0.5f) / 256.0f * 2.0f - 1.0f;
    const float ty1 = ((float)(tileY * TILE + TILE - 1) + 0.5f) / 256.0f * 2.0f - 1.0f;

    const float4* __restrict__ fa = g_fa + b * NF;
    const float4* __restrict__ fb = g_fb + b * NF;
    const float2* __restrict__ fc = g_fc + b * NF;
    const float4* __restrict__ bb = g_bb + b * NF;

    float zmin0 = BIGF, zmin1 = BIGF;
    int   best0 = -1,   best1 = -1;

    const int fbeg = seg * SEGLEN;
    const int fend = min(fbeg + SEGLEN, NF);

    for (int base = fbeg; base < fend; base += CULL) {
        int f = base + tid;
        bool pass = false;
        if (f < fend) {
            float4 bx = bb[f];
            pass = (bx.x <= tx1) & (bx.y >= tx0) & (bx.z <= ty1) & (bx.w >= ty0);
        }
        unsigned m = __ballot_sync(0xffffffffu, pass);
        if (lane == 0) s_wcnt[warp] = __popc(m);
        __syncthreads();

        int off = 0;
        int cnt = 0;
        #pragma unroll
        for (int w = 0; w < NWARPS; w++) {
            int c = s_wcnt[w];
            if (w < warp) off += c;
            cnt += c;
        }
        off += __popc(m & ((1u << lane) - 1u));
        if (pass) {
            s_fa[off] = fa[f];
            s_fb[off] = fb[f];
            s_fc[off] = fc[f];
        }
        __syncthreads();

        for (int k = 0; k < cnt; k++) {
            float4 a  = s_fa[k];
            float4 c4 = s_fb[k];
            float2 e  = s_fc[k];
            float dy  = py  - c4.y;
            float dx0 = px0 - c4.x;
            float dx1 = px1 - c4.x;
            float t0  = a.y * dy;
            float t1  = a.w * dy;
            float w0a = fmaf(a.x, dx0, t0);
            float w0b = fmaf(a.x, dx1, t0);
            float w1a = fmaf(a.z, dx0, t1);
            float w1b = fmaf(a.z, dx1, t1);
            float w2a = 1.0f - w0a - w1a;
            float w2b = 1.0f - w0b - w1b;
            float mna = fminf(fminf(w0a, w1a), w2a);
            float mnb = fminf(fminf(w0b, w1b), w2b);
            float da  = fmaf(w0a, c4.z, fmaf(w1a, c4.w, w2a * e.x));
            float db  = fmaf(w0b, c4.z, fmaf(w1b, c4.w, w2b * e.x));
            bool ua = (mna >= 0.0f) && (da < zmin0);
            bool ub = (mnb >= 0.0f) && (db < zmin1);
            if (ua) { zmin0 = da; best0 = __float_as_int(e.y); }
            if (ub) { zmin1 = db; best1 = __float_as_int(e.y); }
        }
        __syncthreads();
    }

    unsigned long long* zb = g_zb + (size_t)b * PP;
    if (best0 >= 0) {
        unsigned long long key =
            ((unsigned long long)f2sortable(zmin0) << 32) | (unsigned int)best0;
        atomicMin(&zb[py_i * WW + px0_i], key);
    }
    if (best1 >= 0) {
        unsigned long long key =
            ((unsigned long long)f2sortable(zmin1) << 32) | (unsigned int)best1;
        atomicMin(&zb[py_i * WW + px1_i], key);
    }
}

__global__ __launch_bounds__(256) void resolve_kernel(const float* __restrict__ src_img,
                                                      float* __restrict__ out)
{
    const int b   = blockIdx.y;
    const int pix = blockIdx.x * 256 + threadIdx.x;
    const int px_i = pix & (WW - 1);
    const int py_i = pix >> 8;
    const float px = ((float)px_i + 0.5f) / 256.0f * 2.0f - 1.0f;
    const float py = ((float)py_i + 0.5f) / 256.0f * 2.0f - 1.0f;

    unsigned long long key = g_zb[(size_t)b * PP + pix];
    unsigned int face = (unsigned int)(key & 0xFFFFFFFFull);

    float fx, fy;
    if (face != 0xFFFFFFFFu) {
        int gi = b * NF + (int)face;
        float4 a  = g_fa[gi];
        float4 c4 = g_fb[gi];
        float dx = px - c4.x;
        float dy = py - c4.y;
        float w0 = fmaf(a.x, dx, a.y * dy);
        float w1 = fmaf(a.z, dx, a.w * dy);
        float w2 = 1.0f - w0 - w1;
        float2 s0 = g_sf[gi * 3 + 0];
        float2 s1 = g_sf[gi * 3 + 1];
        float2 s2 = g_sf[gi * 3 + 2];
        fx = w0 * s0.x + w1 * s1.x + w2 * s2.x;
        fy = w0 * s0.y + w1 * s1.y + w2 * s2.y;
    } else {
        fx = -2.0f;
        fy = -2.0f;
    }

    float ix = fminf(fmaxf(((fx + 1.0f) * 256.0f - 1.0f) * 0.5f, 0.0f), 255.0f);
    float iy = fminf(fmaxf(((fy + 1.0f) * 256.0f - 1.0f) * 0.5f, 0.0f), 255.0f);
    float x0f = floorf(ix);
    float y0f = floorf(iy);
    float wx = ix - x0f;
    float wy = iy - y0f;
    int x0i = (int)x0f;
    int y0i = (int)y0f;
    int x1i = min(x0i + 1, WW - 1);
    int y1i = min(y0i + 1, HH - 1);

    float wa = (1.0f - wx) * (1.0f - wy);
    float wb = wx * (1.0f - wy);
    float wc = (1.0f - wx) * wy;
    float wd = wx * wy;

    const float* img = src_img + (size_t)b * 3 * HH * WW;
    #pragma unroll
    for (int c = 0; c < 3; c++) {
        const float* p = img + (size_t)c * HH * WW;
        float Ia = p[y0i * WW + x0i];
        float Ib = p[y0i * WW + x1i];
        float Ic = p[y1i * WW + x0i];
        float Id = p[y1i * WW + x1i];
        out[(((size_t)b * 3 + c) * HH + py_i) * WW + px_i] =
            Ia * wa + Ib * wb + Ic * wc + Id * wd;
    }
}

extern "C" void kernel_launch(void* const* d_in, const int* in_sizes, int n_in,
                              void* d_out, int out_size)
{
    const float* src_img   = (const float*)d_in[0];
    const float* src_cam   = (const float*)d_in[1];
    const float* src_verts = (const float*)d_in[2];
    const float* tgt_cam   = (const float*)d_in[3];
    const float* tgt_verts = (const float*)d_in[4];
    const int*   faces     = (const int*)d_in[5];
    float* out = (float*)d_out;

    int n = BATCH * NF;
    setup_kernel<<<(n + 255) / 256, 256>>>(src_cam, src_verts, tgt_cam, tgt_verts, faces);
    zinit_kernel<<<(BATCH * PP + 255) / 256, 256>>>();
    dim3 rgrid(256, NSEG, BATCH);
    raster_kernel<<<rgrid, CULL>>>();
    dim3 ggrid(PP / 256, BATCH);
    resolve_kernel<<<ggrid, 256>>>(src_img, out);
}

// round 3
// speedup vs baseline: 5.4251x; 1.7144x over previous
#include <cuda_runtime.h>

#define HH 256
#define WW 256
#define PP (HH * WW)
#define NF 13776
#define NV 6890
#define BATCH 2
#define BIGF 1000000000.0f
#define EPSF 1e-8f
#define TILE 16
#define NSEG 16
#define SEGLEN ((NF + NSEG - 1) / NSEG)
#define CULL 128
#define NWARPS 4

// Precomputed per-(batch,face) data (SoA, device scratch — no allocs)
__device__ float4 g_fa[BATCH * NF];       // A0*inv, B0*inv, A1*inv, B1*inv
__device__ float4 g_fb[BATCH * NF];       // x2, y2, z0, z1
__device__ float2 g_fc[BATCH * NF];       // z2, face_index (as int bits)
__device__ float4 g_bb[BATCH * NF];       // xmin, xmax, ymin, ymax (empty if degenerate)
__device__ float2 g_sf[BATCH * NF * 3];   // src flow per corner (sx, sy)
__device__ unsigned long long g_zb[BATCH * PP];  // packed (sortable depth << 32) | face

__device__ __forceinline__ unsigned int f2sortable(float d) {
    unsigned int u = __float_as_uint(d);
    return u ^ (((unsigned int)((int)u >> 31)) | 0x80000000u);
}

__global__ void setup_kernel(const float* __restrict__ src_cam,
                             const float* __restrict__ src_verts,
                             const float* __restrict__ tgt_cam,
                             const float* __restrict__ tgt_verts,
                             const int*   __restrict__ faces)
{
    int idx = blockIdx.x * blockDim.x + threadIdx.x;
    if (idx >= BATCH * NF) return;
    int b = idx / NF;
    int f = idx - b * NF;

    int i0 = faces[f * 3 + 0];
    int i1 = faces[f * 3 + 1];
    int i2 = faces[f * 3 + 2];

    float tc0 = tgt_cam[b * 3 + 0];
    float tc1 = tgt_cam[b * 3 + 1];
    float tc2 = tgt_cam[b * 3 + 2];
    const float* tv = tgt_verts + (size_t)b * NV * 3;

    float x0 = tc0 * (tv[i0 * 3 + 0] + tc1);
    float y0 = -(tc0 * (tv[i0 * 3 + 1] + tc2));
    float z0 = tv[i0 * 3 + 2];
    float x1 = tc0 * (tv[i1 * 3 + 0] + tc1);
    float y1 = -(tc0 * (tv[i1 * 3 + 1] + tc2));
    float z1 = tv[i1 * 3 + 2];
    float x2 = tc0 * (tv[i2 * 3 + 0] + tc1);
    float y2 = -(tc0 * (tv[i2 * 3 + 1] + tc2));
    float z2 = tv[i2 * 3 + 2];

    float denom = (y1 - y2) * (x0 - x2) + (x2 - x1) * (y0 - y2);
    bool valid = fabsf(denom) >= EPSF;
    float inv = 1.0f / (valid ? denom : 1.0f);

    g_fa[idx] = make_float4((y1 - y2) * inv, (x2 - x1) * inv,
                            (y2 - y0) * inv, (x0 - x2) * inv);
    g_fb[idx] = make_float4(x2, y2, z0, z1);
    g_fc[idx] = make_float2(z2, __int_as_float(f));

    const float pad = 2.0f / 256.0f;
    float xmn = fminf(x0, fminf(x1, x2)) - pad;
    float xmx = fmaxf(x0, fmaxf(x1, x2)) + pad;
    float ymn = fminf(y0, fminf(y1, y2)) - pad;
    float ymx = fmaxf(y0, fmaxf(y1, y2)) + pad;
    if (!valid) { xmn = 1e30f; xmx = -1e30f; ymn = 1e30f; ymx = -1e30f; }
    g_bb[idx] = make_float4(xmn, xmx, ymn, ymx);

    float sc0 = src_cam[b * 3 + 0];
    float sc1 = src_cam[b * 3 + 1];
    float sc2 = src_cam[b * 3 + 2];
    const float* sv = src_verts + (size_t)b * NV * 3;
    g_sf[idx * 3 + 0] = make_float2(sc0 * (sv[i0 * 3 + 0] + sc1), sc0 * (sv[i0 * 3 + 1] + sc2));
    g_sf[idx * 3 + 1] = make_float2(sc0 * (sv[i1 * 3 + 0] + sc1), sc0 * (sv[i1 * 3 + 1] + sc2));
    g_sf[idx * 3 + 2] = make_float2(sc0 * (sv[i2 * 3 + 0] + sc1), sc0 * (sv[i2 * 3 + 1] + sc2));
}

__global__ void zinit_kernel()
{
    int i = blockIdx.x * blockDim.x + threadIdx.x;
    if (i >= BATCH * PP) return;
    unsigned long long init =
        ((unsigned long long)f2sortable(BIGF) << 32) | 0xFFFFFFFFull;
    g_zb[i] = init;
}

__global__ __launch_bounds__(CULL) void raster_kernel()
{
    __shared__ float4 s_fa[CULL];
    __shared__ float4 s_fb[CULL];
    __shared__ float2 s_fc[CULL];
    __shared__ int    s_wcnt[NWARPS];

    const int b     = blockIdx.z;
    const int seg   = blockIdx.y;
    const int tileX = blockIdx.x & 15;
    const int tileY = blockIdx.x >> 4;
    const int tid   = threadIdx.x;
    const int lane  = tid & 31;
    const int warp  = tid >> 5;

    // two adjacent pixels per thread (row-major within 16x16 tile)
    const int p0    = tid * 2;
    const int px0_i = tileX * TILE + (p0 & 15);
    const int px1_i = px0_i + 1;
    const int py_i  = tileY * TILE + (p0 >> 4);
    const float px0 = ((float)px0_i + 0.5f) / 256.0f * 2.0f - 1.0f;
    const float px1 = ((float)px1_i + 0.5f) / 256.0f * 2.0f - 1.0f;
    const float py  = ((float)py_i + 0.5f) / 256.0f * 2.0f - 1.0f;

    // tile pixel-center rectangle
    const float tx0 = ((float)(tileX * TILE)            + 0.5f) / 256.0f * 2.0f - 1.0f;
    const float tx1 = ((float)(tileX * TILE + TILE - 1) + 0.5f) / 256.0f * 2.0f - 1.0f;
    const float ty0 = ((float)(tileY * TILE)            + 0.5f) / 256.0f * 2.0f - 1.0f;
    const float ty1 = ((float)(tileY * TILE + TILE - 1) + 0.5f) / 256.0f * 2.0f - 1.0f;
    const float cx  = 0.5f * (tx0 + tx1);
    const float cy  = 0.5f * (ty0 + ty1);
    const float hx  = 0.5f * (tx1 - tx0);
    const float hy  = 0.5f * (ty1 - ty0);

    const float4* __restrict__ fa = g_fa + b * NF;
    const float4* __restrict__ fb = g_fb + b * NF;
    const float2* __restrict__ fc = g_fc + b * NF;
    const float4* __restrict__ bb = g_bb + b * NF;

    float zmin0 = BIGF, zmin1 = BIGF;
    int   best0 = -1,   best1 = -1;

    const int fbeg = seg * SEGLEN;
    const int fend = min(fbeg + SEGLEN, NF);

    for (int base = fbeg; base < fend; base += CULL) {
        int f = base + tid;
        bool pass = false;
        if (f < fend) {
            float4 bx = bb[f];
            pass = (bx.x <= tx1) & (bx.y >= tx0) & (bx.z <= ty1) & (bx.w >= ty0);
            if (pass) {
                // conservative half-plane cull: max of each barycentric over the
                // tile's pixel-center rect; reject if any max < 0 (with fp margin)
                float4 a  = fa[f];
                float4 c4 = fb[f];
                float dxc = cx - c4.x;
                float dyc = cy - c4.y;
                float w0c = a.x * dxc + a.y * dyc;
                float w1c = a.z * dxc + a.w * dyc;
                float w2c = 1.0f - w0c - w1c;
                float s0  = fabsf(a.x) * hx + fabsf(a.y) * hy;
                float s1  = fabsf(a.z) * hx + fabsf(a.w) * hy;
                float s2  = fabsf(a.x + a.z) * hx + fabsf(a.y + a.w) * hy;
                float m0  = 1e-5f * (fabsf(w0c) + s0) + 1e-6f;
                float m1  = 1e-5f * (fabsf(w1c) + s1) + 1e-6f;
                float m2  = 1e-5f * (fabsf(w2c) + s2) + 1e-6f;
                pass = (w0c + s0 >= -m0) & (w1c + s1 >= -m1) & (w2c + s2 >= -m2);
            }
        }
        unsigned m = __ballot_sync(0xffffffffu, pass);
        if (lane == 0) s_wcnt[warp] = __popc(m);
        __syncthreads();

        int off = 0;
        int cnt = 0;
        #pragma unroll
        for (int w = 0; w < NWARPS; w++) {
            int c = s_wcnt[w];
            if (w < warp) off += c;
            cnt += c;
        }
        off += __popc(m & ((1u << lane) - 1u));
        if (pass) {
            s_fa[off] = fa[f];
            s_fb[off] = fb[f];
            s_fc[off] = fc[f];
        }
        __syncthreads();

        for (int k = 0; k < cnt; k++) {
            float4 a  = s_fa[k];
            float4 c4 = s_fb[k];
            float2 e  = s_fc[k];
            float dy  = py  - c4.y;
            float dx0 = px0 - c4.x;
            float dx1 = px1 - c4.x;
            float t0  = a.y * dy;
            float t1  = a.w * dy;
            float w0a = fmaf(a.x, dx0, t0);
            float w0b = fmaf(a.x, dx1, t0);
            float w1a = fmaf(a.z, dx0, t1);
            float w1b = fmaf(a.z, dx1, t1);
            float w2a = 1.0f - w0a - w1a;
            float w2b = 1.0f - w0b - w1b;
            float mna = fminf(fminf(w0a, w1a), w2a);
            float mnb = fminf(fminf(w0b, w1b), w2b);
            float da  = fmaf(w0a, c4.z, fmaf(w1a, c4.w, w2a * e.x));
            float db  = fmaf(w0b, c4.z, fmaf(w1b, c4.w, w2b * e.x));
            bool ua = (mna >= 0.0f) && (da < zmin0);
            bool ub = (mnb >= 0.0f) && (db < zmin1);
            if (ua) { zmin0 = da; best0 = __float_as_int(e.y); }
            if (ub) { zmin1 = db; best1 = __float_as_int(e.y); }
        }
        __syncthreads();
    }

    unsigned long long* zb = g_zb + (size_t)b * PP;
    if (best0 >= 0) {
        unsigned long long key =
            ((unsigned long long)f2sortable(zmin0) << 32) | (unsigned int)best0;
        atomicMin(&zb[py_i * WW + px0_i], key);
    }
    if (best1 >= 0) {
        unsigned long long key =
            ((unsigned long long)f2sortable(zmin1) << 32) | (unsigned int)best1;
        atomicMin(&zb[py_i * WW + px1_i], key);
    }
}

__global__ __launch_bounds__(256) void resolve_kernel(const float* __restrict__ src_img,
                                                      float* __restrict__ out)
{
    const int b   = blockIdx.y;
    const int pix = blockIdx.x * 256 + threadIdx.x;
    const int px_i = pix & (WW - 1);
    const int py_i = pix >> 8;
    const float px = ((float)px_i + 0.5f) / 256.0f * 2.0f - 1.0f;
    const float py = ((float)py_i + 0.5f) / 256.0f * 2.0f - 1.0f;

    unsigned long long key = g_zb[(size_t)b * PP + pix];
    unsigned int face = (unsigned int)(key & 0xFFFFFFFFull);

    float fx, fy;
    if (face != 0xFFFFFFFFu) {
        int gi = b * NF + (int)face;
        float4 a  = g_fa[gi];
        float4 c4 = g_fb[gi];
        float dx = px - c4.x;
        float dy = py - c4.y;
        float w0 = fmaf(a.x, dx, a.y * dy);
        float w1 = fmaf(a.z, dx, a.w * dy);
        float w2 = 1.0f - w0 - w1;
        float2 s0 = g_sf[gi * 3 + 0];
        float2 s1 = g_sf[gi * 3 + 1];
        float2 s2 = g_sf[gi * 3 + 2];
        fx = w0 * s0.x + w1 * s1.x + w2 * s2.x;
        fy = w0 * s0.y + w1 * s1.y + w2 * s2.y;
    } else {
        fx = -2.0f;
        fy = -2.0f;
    }

    float ix = fminf(fmaxf(((fx + 1.0f) * 256.0f - 1.0f) * 0.5f, 0.0f), 255.0f);
    float iy = fminf(fmaxf(((fy + 1.0f) * 256.0f - 1.0f) * 0.5f, 0.0f), 255.0f);
    float x0f = floorf(ix);
    float y0f = floorf(iy);
    float wx = ix - x0f;
    float wy = iy - y0f;
    int x0i = (int)x0f;
    int y0i = (int)y0f;
    int x1i = min(x0i + 1, WW - 1);
    int y1i = min(y0i + 1, HH - 1);

    float wa = (1.0f - wx) * (1.0f - wy);
    float wb = wx * (1.0f - wy);
    float wc = (1.0f - wx) * wy;
    float wd = wx * wy;

    const float* img = src_img + (size_t)b * 3 * HH * WW;
    #pragma unroll
    for (int c = 0; c < 3; c++) {
        const float* p = img + (size_t)c * HH * WW;
        float Ia = p[y0i * WW + x0i];
        float Ib = p[y0i * WW + x1i];
        float Ic = p[y1i * WW + x0i];
        float Id = p[y1i * WW + x1i];
        out[(((size_t)b * 3 + c) * HH + py_i) * WW + px_i] =
            Ia * wa + Ib * wb + Ic * wc + Id * wd;
    }
}

extern "C" void kernel_launch(void* const* d_in, const int* in_sizes, int n_in,
                              void* d_out, int out_size)
{
    const float* src_img   = (const float*)d_in[0];
    const float* src_cam   = (const float*)d_in[1];
    const float* src_verts = (const float*)d_in[2];
    const float* tgt_cam   = (const float*)d_in[3];
    const float* tgt_verts = (const float*)d_in[4];
    const int*   faces     = (const int*)d_in[5];
    float* out = (float*)d_out;

    int n = BATCH * NF;
    setup_kernel<<<(n + 255) / 256, 256>>>(src_cam, src_verts, tgt_cam, tgt_verts, faces);
    zinit_kernel<<<(BATCH * PP + 255) / 256, 256>>>();
    dim3 rgrid(256, NSEG, BATCH);
    raster_kernel<<<rgrid, CULL>>>();
    dim3 ggrid(PP / 256, BATCH);
    resolve_kernel<<<ggrid, 256>>>(src_img, out);
}